// round 5
// baseline (speedup 1.0000x reference)
#include <cuda_runtime.h>
#include <cstdint>

// Problem dims (fixed by the dataset)
#define Bv 8
#define Cv 64
#define Hv 256
#define Wv 256
#define HW (Hv * Wv)          // 65536
#define CI_CHUNK 8
#define XS_PITCH 264          // 3 pad | 1 left halo | 256 main | 1 right halo | 3 pad
#define WS_STAGE (CI_CHUNK * 9 * 128)          // 9216 floats per stage
#define XS_STAGE (CI_CHUNK * 4 * XS_PITCH)     // 8448 floats per stage
#define SMEM_FLOATS (2 * (WS_STAGE + XS_STAGE))
#define SMEM_BYTES (SMEM_FLOATS * 4)           // 141312 B
#define EPSV 1e-5f

// ---------------- scratch (no allocations allowed) ----------------
__device__ float g_colsum[Bv * Cv * Wv];   // sum over h of x  [b,c,w]
__device__ float g_fsum[Bv * Cv];
__device__ float g_scores[Bv * Cv];
__device__ float g_wdup[Cv * 9 * 128];     // [(ci*9+k9)*128 + 2*cout] = {w,w}

// ---------------- f32x2 helpers ----------------
__device__ __forceinline__ unsigned long long pk2(float lo, float hi) {
    unsigned long long r;
    asm("mov.b64 %0, {%1, %2};" : "=l"(r) : "f"(lo), "f"(hi));
    return r;
}
__device__ __forceinline__ void unpk2(unsigned long long v, float& lo, float& hi) {
    asm("mov.b64 {%0, %1}, %2;" : "=f"(lo), "=f"(hi) : "l"(v));
}
__device__ __forceinline__ unsigned long long fma2(unsigned long long a,
                                                   unsigned long long b,
                                                   unsigned long long c) {
    unsigned long long d;
    asm("fma.rn.f32x2 %0, %1, %2, %3;" : "=l"(d) : "l"(a), "l"(b), "l"(c));
    return d;
}

// ---------------- cp.async helpers ----------------
__device__ __forceinline__ void cp16(uint32_t dst, const void* src, int srcbytes) {
    asm volatile("cp.async.cg.shared.global [%0], [%1], 16, %2;\n"
                 :: "r"(dst), "l"(src), "r"(srcbytes));
}
__device__ __forceinline__ void cp_commit() {
    asm volatile("cp.async.commit_group;\n" ::: "memory");
}
template <int N>
__device__ __forceinline__ void cp_wait() {
    asm volatile("cp.async.wait_group %0;\n" :: "n"(N) : "memory");
}

// ---------------- kernel 0: pre-transform wv into dup-pair layout ----------------
// g_wdup[(ci*9+k9)*128 + 2*cout] = {wv[cout][ci][k9], same}
__global__ void k_wprep(const float* __restrict__ wv) {
    int r9 = blockIdx.x;          // ci*9 + k9, 0..575
    int cout = threadIdx.x;       // 0..63
    float v = wv[(size_t)cout * 576 + r9];
    *(float2*)&g_wdup[r9 * 128 + 2 * cout] = make_float2(v, v);
}

// ---------------- kernel 1: column sums of x ----------------
__global__ void k_colsum(const float* __restrict__ x) {
    int bc = blockIdx.x;
    int w = threadIdx.x;
    const float* p = x + (size_t)bc * HW + w;
    float s0 = 0.f, s1 = 0.f, s2 = 0.f, s3 = 0.f;
    #pragma unroll 4
    for (int h = 0; h < Hv; h += 4) {
        s0 += p[(h + 0) * Wv];
        s1 += p[(h + 1) * Wv];
        s2 += p[(h + 2) * Wv];
        s3 += p[(h + 3) * Wv];
    }
    g_colsum[bc * Wv + w] = (s0 + s1) + (s2 + s3);
}

// ---------------- kernel 2: f_sum via row-sum identity ----------------
__global__ void k_fsum(const float* __restrict__ x,
                       const float* __restrict__ wq,
                       const float* __restrict__ wk) {
    int c = blockIdx.x, b = blockIdx.y;
    int w = threadIdx.x;
    __shared__ float wqs[576];
    __shared__ float wks[576];
    __shared__ float red[256];
    for (int i = threadIdx.x; i < 576; i += 256) {
        wqs[i] = wq[c * 576 + i];
        wks[i] = wk[c * 576 + i];
    }
    __syncthreads();

    float sq = 0.f, sk = 0.f;
    for (int ci = 0; ci < Cv; ci++) {
        const float* Sc = g_colsum + (b * Cv + ci) * Wv;
        const float* xf = x + (size_t)(b * Cv + ci) * HW;           // row 0
        const float* xl = xf + (Hv - 1) * Wv;                       // row H-1
        const float* q9 = wqs + ci * 9;
        const float* K9 = wks + ci * 9;
        #pragma unroll
        for (int dw = 0; dw < 3; dw++) {
            int wp = w + dw - 1;
            if ((unsigned)wp < (unsigned)Wv) {
                float s = Sc[wp], t = xl[wp], f = xf[wp];
                float q0 = q9[dw], q1 = q9[3 + dw], q2 = q9[6 + dw];
                float k0 = K9[dw], k1 = K9[3 + dw], k2 = K9[6 + dw];
                sq += s * (q0 + q1 + q2) - t * q0 - f * q2;
                sk += s * (k0 + k1 + k2) - t * k0 - f * k2;
            }
        }
    }
    red[w] = sq * sk;
    __syncthreads();
    for (int s = 128; s > 0; s >>= 1) {
        if (w < s) red[w] += red[w + s];
        __syncthreads();
    }
    if (w == 0) g_fsum[b * Cv + c] = red[0] * 0.0625f;   // 1/sqrt(256)
}

// ---------------- kernel 3: softmax over channels ----------------
__global__ void k_softmax() {
    int b = blockIdx.x, t = threadIdx.x;
    __shared__ float sm[64];
    float v = g_fsum[b * Cv + t];
    sm[t] = v;
    __syncthreads();
    for (int s = 32; s > 0; s >>= 1) {
        if (t < s) sm[t] = fmaxf(sm[t], sm[t + s]);
        __syncthreads();
    }
    float m = sm[0];
    __syncthreads();
    float e = expf(v - m);
    sm[t] = e;
    __syncthreads();
    for (int s = 32; s > 0; s >>= 1) {
        if (t < s) sm[t] += sm[t + s];
        __syncthreads();
    }
    g_scores[b * Cv + t] = e / sm[0];
}

// ---------------- kernel 4: fused conv3x3(wv) + epilogue, cp.async pipelined ----------------
// Block: one (b, h-pair). 512 threads: tx=lane covers w=8*tx..8*tx+7,
// ty=0..15 -> couts ty*4..ty*4+3. Double-buffered x/w tiles via cp.async.
// x smem row layout (pitch 264): idx 3 = w-1 halo (const 0), idx 4..259 = w 0..255,
// idx 260 = w=256 halo (const 0). Main region 16B-aligned for LDGSTS.
__global__ void __launch_bounds__(512, 1)
k_convv(const float* __restrict__ x,
        const float* __restrict__ gamma,
        const float* __restrict__ beta,
        const float* __restrict__ rmean,
        const float* __restrict__ rvar,
        float* __restrict__ out) {
    extern __shared__ float smem[];
    float* xs = smem;                         // [2][CI_CHUNK][4][XS_PITCH]
    float* ws = smem + 2 * XS_STAGE;          // [2][WS_STAGE]

    const int h0 = blockIdx.x * 2;
    const int b = blockIdx.y;
    const int tid = threadIdx.x;
    const int tx = tid & 31;
    const int ty = tid >> 5;
    const int cbase = ty * 4;

    // ---- one-time halo zeroing (both stages; never overwritten) ----
    if (tid < 2 * CI_CHUNK * 4) {
        float* row = xs + tid * XS_PITCH;
        row[3] = 0.f;
        row[260] = 0.f;
    }

    // ---- per-thread load geometry ----
    const int rowid = tid >> 4;      // 0..31  -> (ci, r)
    const int q16 = tid & 15;
    const int lci = rowid >> 2;
    const int lr = rowid & 3;
    const int hr = h0 + lr - 1;
    const int okbytes = (hr >= 0 && hr < Hv) ? 16 : 0;
    const int hsafe = (okbytes ? hr : 0);

    auto issue_load = [&](int stage, int cc) {
        // x tile: 8 ci x 4 rows x 256 main cols, 4 float4 per thread
        const float* src = x + ((size_t)(b * Cv + cc * CI_CHUNK + lci) * Hv + hsafe) * Wv;
        float* dstrow = xs + (size_t)stage * XS_STAGE + (lci * 4 + lr) * XS_PITCH + 4;
        #pragma unroll
        for (int j = 0; j < 4; j++) {
            int k = q16 + 16 * j;                 // float4 index 0..63
            uint32_t d = (uint32_t)__cvta_generic_to_shared(dstrow + 4 * k);
            cp16(d, src + 4 * k, okbytes);
        }
        // weight slice: 2304 float4
        const float4* wsrc = (const float4*)(g_wdup + (size_t)cc * WS_STAGE);
        float4* wdst = (float4*)(ws + (size_t)stage * WS_STAGE);
        for (int i = tid; i < WS_STAGE / 4; i += 512) {
            uint32_t d = (uint32_t)__cvta_generic_to_shared(wdst + i);
            cp16(d, wsrc + i, 16);
        }
    };

    unsigned long long acc[2][4][4];   // [outrow][cout][w-pair]
    #pragma unroll
    for (int o = 0; o < 2; o++)
        #pragma unroll
        for (int k = 0; k < 4; k++)
            #pragma unroll
            for (int p = 0; p < 4; p++) acc[o][k][p] = 0ull;

    // ---- pipeline prologue ----
    issue_load(0, 0);
    cp_commit();

    #pragma unroll 1
    for (int cc = 0; cc < Cv / CI_CHUNK; cc++) {
        const int stage = cc & 1;
        __syncthreads();                          // prev compute on (stage^1) done
        if (cc + 1 < Cv / CI_CHUNK) {
            issue_load(stage ^ 1, cc + 1);
            cp_commit();
            cp_wait<1>();                         // stage `cc` data arrived
        } else {
            cp_wait<0>();
        }
        __syncthreads();

        const float* xsb = xs + (size_t)stage * XS_STAGE;
        const float* wsb = ws + (size_t)stage * WS_STAGE;

        #pragma unroll 1
        for (int ci = 0; ci < CI_CHUNK; ci++) {
            #pragma unroll
            for (int rr = 0; rr < 4; rr++) {
                const float* xrow = xsb + (ci * 4 + rr) * XS_PITCH + 3 + 8 * tx;
                float r0 = xrow[0];
                float4 A = *(const float4*)(xrow + 1);
                float4 Bq = *(const float4*)(xrow + 5);
                float r9f = xrow[9];
                float r_[10] = {r0, A.x, A.y, A.z, A.w, Bq.x, Bq.y, Bq.z, Bq.w, r9f};
                unsigned long long v[9];
                #pragma unroll
                for (int j = 0; j < 9; j++) v[j] = pk2(r_[j], r_[j + 1]);

                // out row 0 uses this input row with dh = rr (rr<3)
                if (rr < 3) {
                    const float* wb = wsb + (ci * 9 + rr * 3) * 128 + 2 * cbase;
                    #pragma unroll
                    for (int dw = 0; dw < 3; dw++) {
                        ulonglong2 W01 = *(const ulonglong2*)(wb + dw * 128);
                        ulonglong2 W23 = *(const ulonglong2*)(wb + dw * 128 + 4);
                        #pragma unroll
                        for (int p = 0; p < 4; p++) {
                            acc[0][0][p] = fma2(v[2 * p + dw], W01.x, acc[0][0][p]);
                            acc[0][1][p] = fma2(v[2 * p + dw], W01.y, acc[0][1][p]);
                            acc[0][2][p] = fma2(v[2 * p + dw], W23.x, acc[0][2][p]);
                            acc[0][3][p] = fma2(v[2 * p + dw], W23.y, acc[0][3][p]);
                        }
                    }
                }
                // out row 1 uses this input row with dh = rr-1 (rr>=1)
                if (rr >= 1) {
                    const float* wb = wsb + (ci * 9 + (rr - 1) * 3) * 128 + 2 * cbase;
                    #pragma unroll
                    for (int dw = 0; dw < 3; dw++) {
                        ulonglong2 W01 = *(const ulonglong2*)(wb + dw * 128);
                        ulonglong2 W23 = *(const ulonglong2*)(wb + dw * 128 + 4);
                        #pragma unroll
                        for (int p = 0; p < 4; p++) {
                            acc[1][0][p] = fma2(v[2 * p + dw], W01.x, acc[1][0][p]);
                            acc[1][1][p] = fma2(v[2 * p + dw], W01.y, acc[1][1][p]);
                            acc[1][2][p] = fma2(v[2 * p + dw], W23.x, acc[1][2][p]);
                            acc[1][3][p] = fma2(v[2 * p + dw], W23.y, acc[1][3][p]);
                        }
                    }
                }
            }
        }
    }

    // ---- epilogue: relu( (score*inv)*fv + inv*x + (beta - mean*inv) ) ----
    #pragma unroll
    for (int o = 0; o < 2; o++) {
        int h = h0 + o;
        #pragma unroll
        for (int k = 0; k < 4; k++) {
            int c = cbase + k;
            float inv = gamma[c] * rsqrtf(rvar[c] + EPSV);
            float alpha = g_scores[b * Cv + c] * inv;
            float bias = beta[c] - rmean[c] * inv;
            const float* xrow = x + ((size_t)(b * Cv + c) * Hv + h) * Wv;
            float* orow = out + ((size_t)(b * Cv + c) * Hv + h) * Wv;
            #pragma unroll
            for (int g = 0; g < 2; g++) {       // two float4 groups: pairs (2g, 2g+1)
                float f0lo, f0hi, f1lo, f1hi;
                unpk2(acc[o][k][2 * g + 0], f0lo, f0hi);
                unpk2(acc[o][k][2 * g + 1], f1lo, f1hi);
                int w0 = 8 * tx + 4 * g;
                float4 xr = *(const float4*)(xrow + w0);
                float4 ov;
                ov.x = fmaxf(fmaf(alpha, f0lo, fmaf(inv, xr.x, bias)), 0.f);
                ov.y = fmaxf(fmaf(alpha, f0hi, fmaf(inv, xr.y, bias)), 0.f);
                ov.z = fmaxf(fmaf(alpha, f1lo, fmaf(inv, xr.z, bias)), 0.f);
                ov.w = fmaxf(fmaf(alpha, f1hi, fmaf(inv, xr.w, bias)), 0.f);
                *(float4*)(orow + w0) = ov;
            }
        }
    }
}

// ---------------- launch ----------------
extern "C" void kernel_launch(void* const* d_in, const int* in_sizes, int n_in,
                              void* d_out, int out_size) {
    const float* x     = (const float*)d_in[0];
    const float* wq    = (const float*)d_in[1];
    const float* wk    = (const float*)d_in[2];
    const float* wv    = (const float*)d_in[3];
    const float* gamma = (const float*)d_in[4];
    const float* beta  = (const float*)d_in[5];
    const float* rmean = (const float*)d_in[6];
    const float* rvar  = (const float*)d_in[7];
    float* out = (float*)d_out;

    cudaFuncSetAttribute(k_convv, cudaFuncAttributeMaxDynamicSharedMemorySize,
                         SMEM_BYTES);

    k_wprep<<<576, 64>>>(wv);
    k_colsum<<<Bv * Cv, 256>>>(x);
    k_fsum<<<dim3(Cv, Bv), 256>>>(x, wq, wk);
    k_softmax<<<Bv, 64>>>();
    k_convv<<<dim3(Hv / 2, Bv), 512, SMEM_BYTES>>>(x, gamma, beta, rmean, rvar, out);
}

// round 7
// speedup vs baseline: 2.1594x; 2.1594x over previous
#include <cuda_runtime.h>
#include <cuda_bf16.h>
#include <cstdint>

#define Bv 8
#define Cv 64
#define Hv 256
#define Wv 256
#define HW 65536
#define EPSV 1e-5f

// ---------------- scratch (no allocations allowed) ----------------
__device__ float g_colsum[Bv * Cv * Wv];
__device__ float g_fsum[Bv * Cv];
__device__ float g_scores[Bv * Cv];
// weight fragments: [cc(4)][tap(9)][mt(4)][s(2)][lane(32)] -> uint4 (a0..a3)
__device__ uint4 g_wfrag[4 * 9 * 4 * 2 * 32];

// ---------------- helpers ----------------
__device__ __forceinline__ uint32_t bpack(float flo, float fhi) {
    __nv_bfloat162 t = __floats2bfloat162_rn(flo, fhi);   // x=flo (low), y=fhi (high)
    return *reinterpret_cast<uint32_t*>(&t);
}
__device__ __forceinline__ float bhi(float v) {
    return __bfloat162float(__float2bfloat16(v));
}
__device__ __forceinline__ void mma_bf16(float* c, uint4 a, uint32_t b0, uint32_t b1) {
    asm volatile(
        "mma.sync.aligned.m16n8k16.row.col.f32.bf16.bf16.f32 "
        "{%0,%1,%2,%3}, {%4,%5,%6,%7}, {%8,%9}, {%0,%1,%2,%3};"
        : "+f"(c[0]), "+f"(c[1]), "+f"(c[2]), "+f"(c[3])
        : "r"(a.x), "r"(a.y), "r"(a.z), "r"(a.w), "r"(b0), "r"(b1));
}

// ---------------- kernel 0: weight fragment prep ----------------
// A[r][k] = wv[cout=mt*16+r][ci=cc*16+k][tap]; per-lane m16n8k16 fragment layout:
// a0:(g,2t,2t+1) a1:(g+8,2t,..) a2:(g,2t+8,..) a3:(g+8,2t+8,..); s=0 hi, s=1 lo.
__global__ void k_wfrag(const float* __restrict__ wv) {
    int cc = blockIdx.x, tap = blockIdx.y, mt = blockIdx.z;
    int lane = threadIdx.x, tig = lane & 3, g = lane >> 2;
    float e[4][2];
    #pragma unroll
    for (int rsel = 0; rsel < 4; rsel++) {
        int row = g + (rsel & 1) * 8;
        int k = 2 * tig + (rsel >> 1) * 8;
        int cout = mt * 16 + row;
        e[rsel][0] = wv[(size_t)cout * 576 + (cc * 16 + k) * 9 + tap];
        e[rsel][1] = wv[(size_t)cout * 576 + (cc * 16 + k + 1) * 9 + tap];
    }
    uint32_t h[4], l[4];
    #pragma unroll
    for (int rsel = 0; rsel < 4; rsel++) {
        float h0 = bhi(e[rsel][0]), h1 = bhi(e[rsel][1]);
        h[rsel] = bpack(e[rsel][0], e[rsel][1]);
        l[rsel] = bpack(e[rsel][0] - h0, e[rsel][1] - h1);
    }
    size_t base = (size_t)(((cc * 9 + tap) * 4 + mt) * 2) * 32 + lane;
    g_wfrag[base]      = make_uint4(h[0], h[1], h[2], h[3]);
    g_wfrag[base + 32] = make_uint4(l[0], l[1], l[2], l[3]);
}

// ---------------- kernel 1: column sums ----------------
__global__ void k_colsum(const float* __restrict__ x) {
    int bc = blockIdx.x, w = threadIdx.x;
    const float* p = x + (size_t)bc * HW + w;
    float s0 = 0.f, s1 = 0.f, s2 = 0.f, s3 = 0.f;
    #pragma unroll 4
    for (int h = 0; h < Hv; h += 4) {
        s0 += p[(h + 0) * Wv]; s1 += p[(h + 1) * Wv];
        s2 += p[(h + 2) * Wv]; s3 += p[(h + 3) * Wv];
    }
    g_colsum[bc * Wv + w] = (s0 + s1) + (s2 + s3);
}

// ---------------- kernel 2: f_sum via row-sum identity ----------------
__global__ void k_fsum(const float* __restrict__ x, const float* __restrict__ wq,
                       const float* __restrict__ wk) {
    int c = blockIdx.x, b = blockIdx.y, w = threadIdx.x;
    __shared__ float wqs[576], wks[576], red[256];
    for (int i = w; i < 576; i += 256) { wqs[i] = wq[c * 576 + i]; wks[i] = wk[c * 576 + i]; }
    __syncthreads();
    float sq = 0.f, sk = 0.f;
    for (int ci = 0; ci < Cv; ci++) {
        const float* Sc = g_colsum + (b * Cv + ci) * Wv;
        const float* xf = x + (size_t)(b * Cv + ci) * HW;
        const float* xl = xf + (Hv - 1) * Wv;
        const float* q9 = wqs + ci * 9;
        const float* K9 = wks + ci * 9;
        #pragma unroll
        for (int dw = 0; dw < 3; dw++) {
            int wp = w + dw - 1;
            if ((unsigned)wp < (unsigned)Wv) {
                float s = Sc[wp], t = xl[wp], f = xf[wp];
                float q0 = q9[dw], q1 = q9[3 + dw], q2 = q9[6 + dw];
                float k0 = K9[dw], k1 = K9[3 + dw], k2 = K9[6 + dw];
                sq += s * (q0 + q1 + q2) - t * q0 - f * q2;
                sk += s * (k0 + k1 + k2) - t * k0 - f * k2;
            }
        }
    }
    red[w] = sq * sk;
    __syncthreads();
    for (int s = 128; s > 0; s >>= 1) { if (w < s) red[w] += red[w + s]; __syncthreads(); }
    if (w == 0) g_fsum[b * Cv + c] = red[0] * 0.0625f;
}

// ---------------- kernel 3: softmax over channels ----------------
__global__ void k_softmax() {
    int b = blockIdx.x, t = threadIdx.x;
    __shared__ float sm[64];
    float v = g_fsum[b * Cv + t];
    sm[t] = v; __syncthreads();
    for (int s = 32; s > 0; s >>= 1) { if (t < s) sm[t] = fmaxf(sm[t], sm[t + s]); __syncthreads(); }
    float m = sm[0]; __syncthreads();
    float e = expf(v - m);
    sm[t] = e; __syncthreads();
    for (int s = 32; s > 0; s >>= 1) { if (t < s) sm[t] += sm[t + s]; __syncthreads(); }
    g_scores[b * Cv + t] = e / sm[0];
}

// ---------------- kernel 4: bf16 mma.sync implicit-GEMM conv + epilogue ----------------
// CTA: b x (4 out rows h0..h0+3) x (32 out cols w0..w0+31). M=64 couts, N=128.
// K = 64 ci x 9 taps, 3 bf16 passes (whi*xhi + whi*xlo + wlo*xhi).
// xs smem: [s(2)][row(6)][ci-pair(8)][40] packed bf16x2 (ci even low, odd high);
// j2 = xcol - (w0-4), valid j2 in 0..39; taps index shifted windows.
__global__ void __launch_bounds__(256, 2)
k_conv(const float* __restrict__ x,
       const float* __restrict__ gamma, const float* __restrict__ beta,
       const float* __restrict__ rmean, const float* __restrict__ rvar,
       float* __restrict__ out) {
    __shared__ uint32_t xs[3840];          // 2*6*8*40
    const int tid = threadIdx.x;
    const int lane = tid & 31, wid = tid >> 5;
    const int tig = lane & 3, g = lane >> 2;
    const int mt = wid >> 1, nh = wid & 1;
    const int h0 = blockIdx.x * 4;
    const int w0 = blockIdx.y * 32;
    const int bz = blockIdx.z;

    float acc[8][4];
    #pragma unroll
    for (int i = 0; i < 8; i++)
        #pragma unroll
        for (int j = 0; j < 4; j++) acc[i][j] = 0.f;

    float4 v0[2], v1[2];
    // slots: 8 pairs x 6 rows x 10 col-chunks = 480
    auto ldx = [&](int cc) {
        #pragma unroll
        for (int i = 0; i < 2; i++) {
            int idx = tid + 256 * i;
            float4 a = make_float4(0.f, 0.f, 0.f, 0.f);
            float4 c = make_float4(0.f, 0.f, 0.f, 0.f);
            if (idx < 480) {
                int p = idx / 60, rem = idx - p * 60;
                int r = rem / 10, k = rem - r * 10;
                int hr = h0 - 1 + r;
                int gc = w0 - 4 + 4 * k;
                if (hr >= 0 && hr < Hv && gc >= 0 && gc <= Wv - 4) {
                    const float* src = x + ((size_t)(bz * Cv + cc * 16 + 2 * p) * Hv + hr) * Wv + gc;
                    a = *(const float4*)src;
                    c = *(const float4*)(src + HW);
                }
            }
            v0[i] = a; v1[i] = c;
        }
    };
    auto stx = [&]() {
        #pragma unroll
        for (int i = 0; i < 2; i++) {
            int idx = tid + 256 * i;
            if (idx < 480) {
                int p = idx / 60, rem = idx - p * 60;
                int r = rem / 10, k = rem - r * 10;
                uint32_t off = r * 320 + p * 40 + 4 * k;
                float4 a = v0[i], c = v1[i];
                uint4 H, L;
                H.x = bpack(a.x, c.x); L.x = bpack(a.x - bhi(a.x), c.x - bhi(c.x));
                H.y = bpack(a.y, c.y); L.y = bpack(a.y - bhi(a.y), c.y - bhi(c.y));
                H.z = bpack(a.z, c.z); L.z = bpack(a.z - bhi(a.z), c.z - bhi(c.z));
                H.w = bpack(a.w, c.w); L.w = bpack(a.w - bhi(a.w), c.w - bhi(c.w));
                *(uint4*)&xs[off] = H;
                *(uint4*)&xs[1920 + off] = L;
            }
        }
    };

    ldx(0);
    #pragma unroll 1
    for (int cc = 0; cc < 4; cc++) {
        if (cc) __syncthreads();              // prior mma done reading xs
        stx();
        __syncthreads();                      // xs visible
        if (cc < 3) ldx(cc + 1);              // LDGs fly under the mma below

        const uint4* wb = g_wfrag + (size_t)((cc * 9) * 4 + mt) * 64 + lane;
        uint4 whi = wb[0], wlo = wb[32];
        #pragma unroll
        for (int tap = 0; tap < 9; tap++) {
            const int dh = tap / 3, dw = tap - dh * 3;
            uint4 nhi, nlo;
            if (tap < 8) {
                const uint4* wn = wb + (size_t)(tap + 1) * 256;  // (4 mt)*(2 s)*(32) = 256
                nhi = wn[0]; nlo = wn[32];
            }
            #pragma unroll
            for (int nt = 0; nt < 8; nt++) {
                int oh = nh * 2 + (nt >> 2);
                int r = oh + dh;
                int j2 = 3 + ((nt & 3) << 3) + g + dw;
                const uint32_t* xb = xs + r * 320 + j2;
                uint32_t bh0 = xb[tig * 40];
                uint32_t bh1 = xb[(tig + 4) * 40];
                uint32_t bl0 = xb[1920 + tig * 40];
                uint32_t bl1 = xb[1920 + (tig + 4) * 40];
                mma_bf16(acc[nt], whi, bh0, bh1);
                mma_bf16(acc[nt], whi, bl0, bl1);
                mma_bf16(acc[nt], wlo, bh0, bh1);
            }
            whi = nhi; wlo = nlo;
        }
    }

    // ---- epilogue: relu( (score*inv)*fv + inv*x + (beta - mean*inv) ) ----
    const int c0 = mt * 16 + g, c1 = c0 + 8;
    const float i0 = gamma[c0] * rsqrtf(rvar[c0] + EPSV);
    const float i1 = gamma[c1] * rsqrtf(rvar[c1] + EPSV);
    const float a0 = g_scores[bz * Cv + c0] * i0;
    const float a1 = g_scores[bz * Cv + c1] * i1;
    const float bb0 = beta[c0] - rmean[c0] * i0;
    const float bb1 = beta[c1] - rmean[c1] * i1;
    #pragma unroll
    for (int nt = 0; nt < 8; nt++) {
        int oh = nh * 2 + (nt >> 2);
        int h = h0 + oh;
        int wc = w0 + ((nt & 3) << 3) + 2 * tig;
        size_t o0 = ((size_t)(bz * Cv + c0) * Hv + h) * Wv + wc;
        size_t o1 = ((size_t)(bz * Cv + c1) * Hv + h) * Wv + wc;
        float2 xv0 = *(const float2*)(x + o0);
        float2 xv1 = *(const float2*)(x + o1);
        float2 r0, r1;
        r0.x = fmaxf(fmaf(a0, acc[nt][0], fmaf(i0, xv0.x, bb0)), 0.f);
        r0.y = fmaxf(fmaf(a0, acc[nt][1], fmaf(i0, xv0.y, bb0)), 0.f);
        r1.x = fmaxf(fmaf(a1, acc[nt][2], fmaf(i1, xv1.x, bb1)), 0.f);
        r1.y = fmaxf(fmaf(a1, acc[nt][3], fmaf(i1, xv1.y, bb1)), 0.f);
        *(float2*)(out + o0) = r0;
        *(float2*)(out + o1) = r1;
    }
}

// ---------------- launch ----------------
extern "C" void kernel_launch(void* const* d_in, const int* in_sizes, int n_in,
                              void* d_out, int out_size) {
    const float* x     = (const float*)d_in[0];
    const float* wq    = (const float*)d_in[1];
    const float* wk    = (const float*)d_in[2];
    const float* wv    = (const float*)d_in[3];
    const float* gamma = (const float*)d_in[4];
    const float* beta  = (const float*)d_in[5];
    const float* rmean = (const float*)d_in[6];
    const float* rvar  = (const float*)d_in[7];
    float* out = (float*)d_out;

    k_wfrag<<<dim3(4, 9, 4), 32>>>(wv);
    k_colsum<<<Bv * Cv, 256>>>(x);
    k_fsum<<<dim3(Cv, Bv), 256>>>(x, wq, wk);
    k_softmax<<<Bv, 64>>>();
    k_conv<<<dim3(Hv / 4, Wv / 32, Bv), 256>>>(x, gamma, beta, rmean, rvar, out);
}

// round 8
// speedup vs baseline: 4.7125x; 2.1823x over previous
#include <cuda_runtime.h>
#include <cuda_fp16.h>
#include <cstdint>

#define Bv 8
#define Cv 64
#define Hv 256
#define Wv 256
#define HW 65536
#define EPSV 1e-5f

// ---------------- scratch (no allocations allowed) ----------------
__device__ float g_colsum[Bv * Cv * Wv];
__device__ float g_fsum[Bv * Cv];
__device__ float g_scores[Bv * Cv];
// weight fragments (fp16): [cc(4)][tap(9)][mt(4)][lane(32)] -> uint4 (a0..a3)
__device__ uint4 g_wfrag[4 * 9 * 4 * 32];

// ---------------- helpers ----------------
__device__ __forceinline__ uint32_t hpack(float lo, float hi) {
    __half2 t = __floats2half2_rn(lo, hi);     // x=lo, y=hi
    return *reinterpret_cast<uint32_t*>(&t);
}
__device__ __forceinline__ void mma_f16(float* c, uint4 a, uint32_t b0, uint32_t b1) {
    asm volatile(
        "mma.sync.aligned.m16n8k16.row.col.f32.f16.f16.f32 "
        "{%0,%1,%2,%3}, {%4,%5,%6,%7}, {%8,%9}, {%0,%1,%2,%3};"
        : "+f"(c[0]), "+f"(c[1]), "+f"(c[2]), "+f"(c[3])
        : "r"(a.x), "r"(a.y), "r"(a.z), "r"(a.w), "r"(b0), "r"(b1));
}

// ---------------- kernel 0: weight fragment prep ----------------
// A[r][k] = wv[cout=mt*16+r][ci=cc*16+k][tap]; m16n8k16 A fragment per lane:
// a0:(g, 2t..2t+1) a1:(g+8, 2t..) a2:(g, 2t+8..) a3:(g+8, 2t+8..)
__global__ void k_wfrag(const float* __restrict__ wv) {
    int cc = blockIdx.x, tap = blockIdx.y, mt = blockIdx.z;
    int lane = threadIdx.x, tig = lane & 3, g = lane >> 2;
    uint32_t h[4];
    #pragma unroll
    for (int rsel = 0; rsel < 4; rsel++) {
        int row = g + (rsel & 1) * 8;
        int k = 2 * tig + (rsel >> 1) * 8;
        int cout = mt * 16 + row;
        float e0 = wv[(size_t)cout * 576 + (cc * 16 + k) * 9 + tap];
        float e1 = wv[(size_t)cout * 576 + (cc * 16 + k + 1) * 9 + tap];
        h[rsel] = hpack(e0, e1);
    }
    g_wfrag[(size_t)(((cc * 9 + tap) * 4 + mt)) * 32 + lane] =
        make_uint4(h[0], h[1], h[2], h[3]);
}

// ---------------- kernel 1: column sums ----------------
__global__ void k_colsum(const float* __restrict__ x) {
    int bc = blockIdx.x, w = threadIdx.x;
    const float* p = x + (size_t)bc * HW + w;
    float s0 = 0.f, s1 = 0.f, s2 = 0.f, s3 = 0.f;
    #pragma unroll 4
    for (int h = 0; h < Hv; h += 4) {
        s0 += p[(h + 0) * Wv]; s1 += p[(h + 1) * Wv];
        s2 += p[(h + 2) * Wv]; s3 += p[(h + 3) * Wv];
    }
    g_colsum[bc * Wv + w] = (s0 + s1) + (s2 + s3);
}

// ---------------- kernel 2: f_sum via row-sum identity ----------------
__global__ void k_fsum(const float* __restrict__ x, const float* __restrict__ wq,
                       const float* __restrict__ wk) {
    int c = blockIdx.x, b = blockIdx.y, w = threadIdx.x;
    __shared__ float wqs[576], wks[576], red[256];
    for (int i = w; i < 576; i += 256) { wqs[i] = wq[c * 576 + i]; wks[i] = wk[c * 576 + i]; }
    __syncthreads();
    float sq = 0.f, sk = 0.f;
    for (int ci = 0; ci < Cv; ci++) {
        const float* Sc = g_colsum + (b * Cv + ci) * Wv;
        const float* xf = x + (size_t)(b * Cv + ci) * HW;
        const float* xl = xf + (Hv - 1) * Wv;
        const float* q9 = wqs + ci * 9;
        const float* K9 = wks + ci * 9;
        #pragma unroll
        for (int dw = 0; dw < 3; dw++) {
            int wp = w + dw - 1;
            if ((unsigned)wp < (unsigned)Wv) {
                float s = Sc[wp], t = xl[wp], f = xf[wp];
                float q0 = q9[dw], q1 = q9[3 + dw], q2 = q9[6 + dw];
                float k0 = K9[dw], k1 = K9[3 + dw], k2 = K9[6 + dw];
                sq += s * (q0 + q1 + q2) - t * q0 - f * q2;
                sk += s * (k0 + k1 + k2) - t * k0 - f * k2;
            }
        }
    }
    red[w] = sq * sk;
    __syncthreads();
    for (int s = 128; s > 0; s >>= 1) { if (w < s) red[w] += red[w + s]; __syncthreads(); }
    if (w == 0) g_fsum[b * Cv + c] = red[0] * 0.0625f;
}

// ---------------- kernel 3: softmax over channels ----------------
__global__ void k_softmax() {
    int b = blockIdx.x, t = threadIdx.x;
    __shared__ float sm[64];
    float v = g_fsum[b * Cv + t];
    sm[t] = v; __syncthreads();
    for (int s = 32; s > 0; s >>= 1) { if (t < s) sm[t] = fmaxf(sm[t], sm[t + s]); __syncthreads(); }
    float m = sm[0]; __syncthreads();
    float e = expf(v - m);
    sm[t] = e; __syncthreads();
    for (int s = 32; s > 0; s >>= 1) { if (t < s) sm[t] += sm[t + s]; __syncthreads(); }
    g_scores[b * Cv + t] = e / sm[0];
}

// ---------------- kernel 4: fp16 mma.sync implicit-GEMM conv + epilogue ----------------
// CTA: b x (4 out rows) x (32 out cols). M=64 couts, N=128 (4 rows x 32 cols).
// K = 64 ci x 9 taps, SINGLE fp16 pass (rel err ~1e-4, threshold 1e-3).
// xs smem: [row(6)][ci-pair(8)][40] half2 (ci even=lo, odd=hi);
// j2 = xcol - (w0-4); taps index shifted windows; stride-40 rows conflict-free.
__global__ void __launch_bounds__(256, 3)
k_conv(const float* __restrict__ x,
       const float* __restrict__ gamma, const float* __restrict__ beta,
       const float* __restrict__ rmean, const float* __restrict__ rvar,
       float* __restrict__ out) {
    __shared__ uint32_t xs[1920];          // 6*8*40
    const int tid = threadIdx.x;
    const int lane = tid & 31, wid = tid >> 5;
    const int tig = lane & 3, g = lane >> 2;
    const int mt = wid >> 1, nh = wid & 1;
    const int h0 = blockIdx.x * 4;
    const int w0 = blockIdx.y * 32;
    const int bz = blockIdx.z;

    float acc[8][4];
    #pragma unroll
    for (int i = 0; i < 8; i++)
        #pragma unroll
        for (int j = 0; j < 4; j++) acc[i][j] = 0.f;

    float4 v0[2], v1[2];
    // slots: 8 ci-pairs x 6 rows x 10 col-chunks = 480
    auto ldx = [&](int cc) {
        #pragma unroll
        for (int i = 0; i < 2; i++) {
            int idx = tid + 256 * i;
            float4 a = make_float4(0.f, 0.f, 0.f, 0.f);
            float4 c = make_float4(0.f, 0.f, 0.f, 0.f);
            if (idx < 480) {
                int p = idx / 60, rem = idx - p * 60;
                int r = rem / 10, k = rem - r * 10;
                int hr = h0 - 1 + r;
                int gc = w0 - 4 + 4 * k;
                if (hr >= 0 && hr < Hv && gc >= 0 && gc <= Wv - 4) {
                    const float* src = x + ((size_t)(bz * Cv + cc * 16 + 2 * p) * Hv + hr) * Wv + gc;
                    a = *(const float4*)src;
                    c = *(const float4*)(src + HW);
                }
            }
            v0[i] = a; v1[i] = c;
        }
    };
    auto stx = [&]() {
        #pragma unroll
        for (int i = 0; i < 2; i++) {
            int idx = tid + 256 * i;
            if (idx < 480) {
                int p = idx / 60, rem = idx - p * 60;
                int r = rem / 10, k = rem - r * 10;
                uint32_t off = r * 320 + p * 40 + 4 * k;
                float4 a = v0[i], c = v1[i];
                uint4 H;
                H.x = hpack(a.x, c.x);
                H.y = hpack(a.y, c.y);
                H.z = hpack(a.z, c.z);
                H.w = hpack(a.w, c.w);
                *(uint4*)&xs[off] = H;
            }
        }
    };

    ldx(0);
    #pragma unroll 1
    for (int cc = 0; cc < 4; cc++) {
        if (cc) __syncthreads();              // prior mma done reading xs
        stx();
        __syncthreads();                      // xs visible
        if (cc < 3) ldx(cc + 1);              // LDGs fly under the mma below

        const uint4* wb = g_wfrag + (size_t)((cc * 9) * 4 + mt) * 32 + lane;
        uint4 wf = wb[0];
        #pragma unroll
        for (int tap = 0; tap < 9; tap++) {
            const int dh = tap / 3, dw = tap - dh * 3;
            uint4 wn;
            if (tap < 8) wn = wb[(size_t)(tap + 1) * 128];   // (4 mt)*(32 lanes)
            #pragma unroll
            for (int nt = 0; nt < 8; nt++) {
                int oh = nh * 2 + (nt >> 2);
                int r = oh + dh;
                int j2 = 3 + ((nt & 3) << 3) + g + dw;
                const uint32_t* xb = xs + r * 320 + j2;
                uint32_t b0 = xb[tig * 40];
                uint32_t b1 = xb[(tig + 4) * 40];
                mma_f16(acc[nt], wf, b0, b1);
            }
            wf = wn;
        }
    }

    // ---- epilogue: relu( (score*inv)*fv + inv*x + (beta - mean*inv) ) ----
    const int c0 = mt * 16 + g, c1 = c0 + 8;
    const float i0 = gamma[c0] * rsqrtf(rvar[c0] + EPSV);
    const float i1 = gamma[c1] * rsqrtf(rvar[c1] + EPSV);
    const float a0 = g_scores[bz * Cv + c0] * i0;
    const float a1 = g_scores[bz * Cv + c1] * i1;
    const float bb0 = beta[c0] - rmean[c0] * i0;
    const float bb1 = beta[c1] - rmean[c1] * i1;
    #pragma unroll
    for (int nt = 0; nt < 8; nt++) {
        int oh = nh * 2 + (nt >> 2);
        int h = h0 + oh;
        int wc = w0 + ((nt & 3) << 3) + 2 * tig;
        size_t o0 = ((size_t)(bz * Cv + c0) * Hv + h) * Wv + wc;
        size_t o1 = ((size_t)(bz * Cv + c1) * Hv + h) * Wv + wc;
        float2 xv0 = *(const float2*)(x + o0);
        float2 xv1 = *(const float2*)(x + o1);
        float2 r0, r1;
        r0.x = fmaxf(fmaf(a0, acc[nt][0], fmaf(i0, xv0.x, bb0)), 0.f);
        r0.y = fmaxf(fmaf(a0, acc[nt][1], fmaf(i0, xv0.y, bb0)), 0.f);
        r1.x = fmaxf(fmaf(a1, acc[nt][2], fmaf(i1, xv1.x, bb1)), 0.f);
        r1.y = fmaxf(fmaf(a1, acc[nt][3], fmaf(i1, xv1.y, bb1)), 0.f);
        *(float2*)(out + o0) = r0;
        *(float2*)(out + o1) = r1;
    }
}

// ---------------- launch ----------------
extern "C" void kernel_launch(void* const* d_in, const int* in_sizes, int n_in,
                              void* d_out, int out_size) {
    const float* x     = (const float*)d_in[0];
    const float* wq    = (const float*)d_in[1];
    const float* wk    = (const float*)d_in[2];
    const float* wv    = (const float*)d_in[3];
    const float* gamma = (const float*)d_in[4];
    const float* beta  = (const float*)d_in[5];
    const float* rmean = (const float*)d_in[6];
    const float* rvar  = (const float*)d_in[7];
    float* out = (float*)d_out;

    k_wfrag<<<dim3(4, 9, 4), 32>>>(wv);
    k_colsum<<<Bv * Cv, 256>>>(x);
    k_fsum<<<dim3(Cv, Bv), 256>>>(x, wq, wk);
    k_softmax<<<Bv, 64>>>();
    k_conv<<<dim3(Hv / 4, Wv / 32, Bv), 256>>>(x, gamma, beta, rmean, rvar, out);
}

// round 9
// speedup vs baseline: 4.7660x; 1.0114x over previous
#include <cuda_runtime.h>
#include <cuda_fp16.h>
#include <cstdint>

#define Bv 8
#define Cv 64
#define Hv 256
#define Wv 256
#define HW 65536
#define EPSV 1e-5f

// ---------------- scratch (no allocations allowed) ----------------
__device__ float g_colsum[Bv * Cv * Wv];
__device__ float g_fsum[Bv * Cv];
// weight fragments (fp16): [cc(4)][tap(9)][mt(4)][lane(32)] -> uint4 (a0..a3)
__device__ uint4 g_wfrag[4 * 9 * 4 * 32];

// ---------------- helpers ----------------
__device__ __forceinline__ uint32_t hpack(float lo, float hi) {
    __half2 t = __floats2half2_rn(lo, hi);     // x=lo, y=hi
    return *reinterpret_cast<uint32_t*>(&t);
}
__device__ __forceinline__ void mma_f16(float* c, uint4 a, uint32_t b0, uint32_t b1) {
    asm volatile(
        "mma.sync.aligned.m16n8k16.row.col.f32.f16.f16.f32 "
        "{%0,%1,%2,%3}, {%4,%5,%6,%7}, {%8,%9}, {%0,%1,%2,%3};"
        : "+f"(c[0]), "+f"(c[1]), "+f"(c[2]), "+f"(c[3])
        : "r"(a.x), "r"(a.y), "r"(a.z), "r"(a.w), "r"(b0), "r"(b1));
}

// ---------------- kernel 1: column sums of x  +  weight fragment prep ----------------
// blocks 0..511: colsum for (b,c) = blockIdx.x. blocks 512..529: wfrag.
__global__ void k_colsum_wfrag(const float* __restrict__ x,
                               const float* __restrict__ wv) {
    if (blockIdx.x < 512) {
        int bc = blockIdx.x, w = threadIdx.x;
        const float* p = x + (size_t)bc * HW + w;
        float s0 = 0.f, s1 = 0.f, s2 = 0.f, s3 = 0.f;
        #pragma unroll 4
        for (int h = 0; h < Hv; h += 4) {
            s0 += p[(h + 0) * Wv]; s1 += p[(h + 1) * Wv];
            s2 += p[(h + 2) * Wv]; s3 += p[(h + 3) * Wv];
        }
        g_colsum[bc * Wv + w] = (s0 + s1) + (s2 + s3);
    } else {
        // weight fragments: combo = (cc*9 + tap)*4 + mt, 144 combos over 18 blocks x 8 warps
        int wid = threadIdx.x >> 5, lane = threadIdx.x & 31;
        int combo = (blockIdx.x - 512) * 8 + wid;
        int cc = combo / 36, r = combo % 36, tap = r >> 2, mt = r & 3;
        int tig = lane & 3, g = lane >> 2;
        uint32_t h[4];
        #pragma unroll
        for (int rsel = 0; rsel < 4; rsel++) {
            int row = g + (rsel & 1) * 8;
            int k = 2 * tig + (rsel >> 1) * 8;
            int cout = mt * 16 + row;
            float e0 = wv[(size_t)cout * 576 + (cc * 16 + k) * 9 + tap];
            float e1 = wv[(size_t)cout * 576 + (cc * 16 + k + 1) * 9 + tap];
            h[rsel] = hpack(e0, e1);
        }
        g_wfrag[(size_t)combo * 32 + lane] = make_uint4(h[0], h[1], h[2], h[3]);
    }
}

// ---------------- kernel 2: f_sum via row-sum identity ----------------
__global__ void k_fsum(const float* __restrict__ x, const float* __restrict__ wq,
                       const float* __restrict__ wk) {
    int c = blockIdx.x, b = blockIdx.y, w = threadIdx.x;
    __shared__ float wqs[576], wks[576], red[256];
    for (int i = w; i < 576; i += 256) { wqs[i] = wq[c * 576 + i]; wks[i] = wk[c * 576 + i]; }
    __syncthreads();
    float sq = 0.f, sk = 0.f;
    for (int ci = 0; ci < Cv; ci++) {
        const float* Sc = g_colsum + (b * Cv + ci) * Wv;
        const float* xf = x + (size_t)(b * Cv + ci) * HW;
        const float* xl = xf + (Hv - 1) * Wv;
        const float* q9 = wqs + ci * 9;
        const float* K9 = wks + ci * 9;
        #pragma unroll
        for (int dw = 0; dw < 3; dw++) {
            int wp = w + dw - 1;
            if ((unsigned)wp < (unsigned)Wv) {
                float s = Sc[wp], t = xl[wp], f = xf[wp];
                float q0 = q9[dw], q1 = q9[3 + dw], q2 = q9[6 + dw];
                float k0 = K9[dw], k1 = K9[3 + dw], k2 = K9[6 + dw];
                sq += s * (q0 + q1 + q2) - t * q0 - f * q2;
                sk += s * (k0 + k1 + k2) - t * k0 - f * k2;
            }
        }
    }
    red[w] = sq * sk;
    __syncthreads();
    for (int s = 128; s > 0; s >>= 1) { if (w < s) red[w] += red[w + s]; __syncthreads(); }
    if (w == 0) g_fsum[b * Cv + c] = red[0] * 0.0625f;
}

// ---------------- kernel 3: fp16 mma.sync implicit-GEMM conv + softmax + epilogue ----------------
// CTA: b x (4 out rows) x (32 out cols). M=64 couts, N=128 (4 rows x 32 cols).
// K = 64 ci x 9 taps, single fp16 pass. Inline channel softmax (warp 0).
// xs double-buffered: [2][row(6)][ci-pair(8)][40] half2; one barrier per cc.
__global__ void __launch_bounds__(256, 3)
k_conv(const float* __restrict__ x,
       const float* __restrict__ gamma, const float* __restrict__ beta,
       const float* __restrict__ rmean, const float* __restrict__ rvar,
       float* __restrict__ out) {
    __shared__ uint32_t xs[2][1920];          // 2 x 6*8*40
    __shared__ float sc[64];
    const int tid = threadIdx.x;
    const int lane = tid & 31, wid = tid >> 5;
    const int tig = lane & 3, g = lane >> 2;
    const int mt = wid >> 1, nh = wid & 1;
    const int h0 = blockIdx.x * 4;
    const int w0 = blockIdx.y * 32;
    const int bz = blockIdx.z;

    // ---- inline softmax over 64 channels (warp 0) ----
    if (wid == 0) {
        float va = g_fsum[bz * Cv + lane];
        float vb = g_fsum[bz * Cv + 32 + lane];
        float m = fmaxf(va, vb);
        #pragma unroll
        for (int off = 16; off > 0; off >>= 1)
            m = fmaxf(m, __shfl_xor_sync(0xFFFFFFFFu, m, off));
        float ea = expf(va - m), eb = expf(vb - m);
        float s = ea + eb;
        #pragma unroll
        for (int off = 16; off > 0; off >>= 1)
            s += __shfl_xor_sync(0xFFFFFFFFu, s, off);
        sc[lane] = ea / s;
        sc[lane + 32] = eb / s;
    }

    float acc[8][4];
    #pragma unroll
    for (int i = 0; i < 8; i++)
        #pragma unroll
        for (int j = 0; j < 4; j++) acc[i][j] = 0.f;

    float4 v0[2], v1[2];
    // slots: 8 ci-pairs x 6 rows x 10 col-chunks = 480
    auto ldx = [&](int cc) {
        #pragma unroll
        for (int i = 0; i < 2; i++) {
            int idx = tid + 256 * i;
            float4 a = make_float4(0.f, 0.f, 0.f, 0.f);
            float4 c = make_float4(0.f, 0.f, 0.f, 0.f);
            if (idx < 480) {
                int p = idx / 60, rem = idx - p * 60;
                int r = rem / 10, k = rem - r * 10;
                int hr = h0 - 1 + r;
                int gc = w0 - 4 + 4 * k;
                if (hr >= 0 && hr < Hv && gc >= 0 && gc <= Wv - 4) {
                    const float* src = x + ((size_t)(bz * Cv + cc * 16 + 2 * p) * Hv + hr) * Wv + gc;
                    a = *(const float4*)src;
                    c = *(const float4*)(src + HW);
                }
            }
            v0[i] = a; v1[i] = c;
        }
    };
    auto stx = [&](int buf) {
        #pragma unroll
        for (int i = 0; i < 2; i++) {
            int idx = tid + 256 * i;
            if (idx < 480) {
                int p = idx / 60, rem = idx - p * 60;
                int r = rem / 10, k = rem - r * 10;
                uint32_t off = r * 320 + p * 40 + 4 * k;
                float4 a = v0[i], c = v1[i];
                uint4 H;
                H.x = hpack(a.x, c.x);
                H.y = hpack(a.y, c.y);
                H.z = hpack(a.z, c.z);
                H.w = hpack(a.w, c.w);
                *(uint4*)&xs[buf][off] = H;
            }
        }
    };

    ldx(0);
    stx(0);
    __syncthreads();                         // xs[0] + sc ready
    #pragma unroll 1
    for (int cc = 0; cc < 4; cc++) {
        const int buf = cc & 1;
        if (cc < 3) ldx(cc + 1);             // LDGs fly under the mma below

        const uint4* wb = g_wfrag + (size_t)((cc * 9) * 4 + mt) * 32 + lane;
        uint4 wf = wb[0];
        #pragma unroll
        for (int tap = 0; tap < 9; tap++) {
            const int dh = tap / 3, dw = tap - dh * 3;
            uint4 wn;
            if (tap < 8) wn = wb[(size_t)(tap + 1) * 128];   // (4 mt)*(32 lanes)
            #pragma unroll
            for (int nt = 0; nt < 8; nt++) {
                int oh = nh * 2 + (nt >> 2);
                int r = oh + dh;
                int j2 = 3 + ((nt & 3) << 3) + g + dw;
                const uint32_t* xb = xs[buf] + r * 320 + j2;
                uint32_t b0 = xb[tig * 40];
                uint32_t b1 = xb[(tig + 4) * 40];
                mma_f16(acc[nt], wf, b0, b1);
            }
            wf = wn;
        }
        if (cc < 3) {
            stx(buf ^ 1);                    // other buffer: drained since cc-1 barrier
            __syncthreads();                 // xs[buf^1] ready
        }
    }

    // ---- epilogue: relu( (score*inv)*fv + inv*x + (beta - mean*inv) ) ----
    const int c0 = mt * 16 + g, c1 = c0 + 8;
    const float i0 = gamma[c0] * rsqrtf(rvar[c0] + EPSV);
    const float i1 = gamma[c1] * rsqrtf(rvar[c1] + EPSV);
    const float a0 = sc[c0] * i0;
    const float a1 = sc[c1] * i1;
    const float bb0 = beta[c0] - rmean[c0] * i0;
    const float bb1 = beta[c1] - rmean[c1] * i1;
    #pragma unroll
    for (int nt = 0; nt < 8; nt++) {
        int oh = nh * 2 + (nt >> 2);
        int h = h0 + oh;
        int wc = w0 + ((nt & 3) << 3) + 2 * tig;
        size_t o0 = ((size_t)(bz * Cv + c0) * Hv + h) * Wv + wc;
        size_t o1 = ((size_t)(bz * Cv + c1) * Hv + h) * Wv + wc;
        float2 xv0 = *(const float2*)(x + o0);
        float2 xv1 = *(const float2*)(x + o1);
        float2 r0, r1;
        r0.x = fmaxf(fmaf(a0, acc[nt][0], fmaf(i0, xv0.x, bb0)), 0.f);
        r0.y = fmaxf(fmaf(a0, acc[nt][1], fmaf(i0, xv0.y, bb0)), 0.f);
        r1.x = fmaxf(fmaf(a1, acc[nt][2], fmaf(i1, xv1.x, bb1)), 0.f);
        r1.y = fmaxf(fmaf(a1, acc[nt][3], fmaf(i1, xv1.y, bb1)), 0.f);
        *(float2*)(out + o0) = r0;
        *(float2*)(out + o1) = r1;
    }
}

// ---------------- launch ----------------
extern "C" void kernel_launch(void* const* d_in, const int* in_sizes, int n_in,
                              void* d_out, int out_size) {
    const float* x     = (const float*)d_in[0];
    const float* wq    = (const float*)d_in[1];
    const float* wk    = (const float*)d_in[2];
    const float* wv    = (const float*)d_in[3];
    const float* gamma = (const float*)d_in[4];
    const float* beta  = (const float*)d_in[5];
    const float* rmean = (const float*)d_in[6];
    const float* rvar  = (const float*)d_in[7];
    float* out = (float*)d_out;

    k_colsum_wfrag<<<530, 256>>>(x, wv);
    k_fsum<<<dim3(Cv, Bv), 256>>>(x, wq, wk);
    k_conv<<<dim3(Hv / 4, Wv / 32, Bv), 256>>>(x, gamma, beta, rmean, rvar, out);
}